// round 4
// baseline (speedup 1.0000x reference)
#include <cuda_runtime.h>
#include <cuda_bf16.h>
#include <math.h>

#define MAX_NODES 50000
#define NF 128
#define N_GRAPHS 64

// ---------------- scratch (device-symbol globals; referenced ONLY in device code) ----------------
__device__ float g_deg[MAX_NODES];
__device__ float g_dinv[MAX_NODES];
__device__ float g_xw[(size_t)MAX_NODES * NF];   // x@W result
__device__ float g_h[(size_t)MAX_NODES * NF];    // aggregated hidden
__device__ float g_pooled[N_GRAPHS * NF];
__device__ float g_cnt[N_GRAPHS];

// ---------------- degree / norm ----------------
__global__ void k_deg_init(int n) {
    int i = blockIdx.x * blockDim.x + threadIdx.x;
    if (i < n) g_deg[i] = 1.0f;  // self-loop
}

__global__ void k_deg_edges(const int* __restrict__ dst, int E) {
    int i = blockIdx.x * blockDim.x + threadIdx.x;
    if (i < E) atomicAdd(&g_deg[dst[i]], 1.0f);
}

__global__ void k_dinv(int n) {
    int i = blockIdx.x * blockDim.x + threadIdx.x;
    if (i < n) g_dinv[i] = rsqrtf(g_deg[i]);  // deg >= 1 always
}

// ---------------- GEMM: g_xw[n,128] = A[n,128] @ W[128,128] ----------------
// A = external x (fromH=0) or g_h (fromH=1).
// block: 256 threads, tile 64 rows x 128 cols, each thread 8 rows x 4 cols
__global__ __launch_bounds__(256) void k_gemm(const float* __restrict__ A_ext,
                                              const float* __restrict__ W,
                                              int n, int fromH) {
    const float* A = fromH ? g_h : A_ext;
    __shared__ float As[64][NF];   // 32 KB
    __shared__ float Ws[32][NF];   // 16 KB
    const int tid = threadIdx.x;
    const int row0 = blockIdx.x * 64;
    const int tx = tid & 31;       // col group: cols tx*4..tx*4+3
    const int ty = tid >> 5;       // row group: rows ty*8..ty*8+7

    // load A tile (guard rows)
    for (int i = tid; i < 64 * 32; i += 256) {   // float4 units
        int r = i >> 5, c4 = i & 31;
        float4 v = make_float4(0.f, 0.f, 0.f, 0.f);
        if (row0 + r < n)
            v = reinterpret_cast<const float4*>(A + (size_t)(row0 + r) * NF)[c4];
        *reinterpret_cast<float4*>(&As[r][c4 * 4]) = v;
    }

    float acc[8][4];
#pragma unroll
    for (int r = 0; r < 8; r++)
#pragma unroll
        for (int c = 0; c < 4; c++) acc[r][c] = 0.f;

    for (int kc = 0; kc < 4; kc++) {             // 4 chunks of K=32
        __syncthreads();
        for (int i = tid; i < 32 * 32; i += 256) {  // float4 units
            int r = i >> 5, c4 = i & 31;
            *reinterpret_cast<float4*>(&Ws[r][c4 * 4]) =
                reinterpret_cast<const float4*>(W + (size_t)(kc * 32 + r) * NF)[c4];
        }
        __syncthreads();
#pragma unroll
        for (int k = 0; k < 32; k++) {
            float4 w = *reinterpret_cast<const float4*>(&Ws[k][tx * 4]);
#pragma unroll
            for (int r = 0; r < 8; r++) {
                float a = As[ty * 8 + r][kc * 32 + k];
                acc[r][0] = fmaf(a, w.x, acc[r][0]);
                acc[r][1] = fmaf(a, w.y, acc[r][1]);
                acc[r][2] = fmaf(a, w.z, acc[r][2]);
                acc[r][3] = fmaf(a, w.w, acc[r][3]);
            }
        }
    }

#pragma unroll
    for (int r = 0; r < 8; r++) {
        int row = row0 + ty * 8 + r;
        if (row < n) {
            float4 v = make_float4(acc[r][0], acc[r][1], acc[r][2], acc[r][3]);
            reinterpret_cast<float4*>(g_xw + (size_t)row * NF)[tx] = v;
        }
    }
}

// ---------------- self-loop + bias init: g_h = dinv^2 * g_xw + b ----------------
__global__ void k_selfinit(const float* __restrict__ b, int n) {
    int idx = blockIdx.x * blockDim.x + threadIdx.x;   // float4 index
    int total = n * (NF / 4);
    if (idx >= total) return;
    int node = idx >> 5;        // /32
    int c4 = idx & 31;
    float d = g_dinv[node];
    float w = d * d;
    float4 v = reinterpret_cast<const float4*>(g_xw)[idx];
    float4 bb = reinterpret_cast<const float4*>(b)[c4];
    float4 o;
    o.x = fmaf(w, v.x, bb.x);
    o.y = fmaf(w, v.y, bb.y);
    o.z = fmaf(w, v.z, bb.z);
    o.w = fmaf(w, v.w, bb.w);
    reinterpret_cast<float4*>(g_h)[idx] = o;
}

// ---------------- edge scatter: g_h[dst] += dinv[s]*dinv[d]*g_xw[src] ----------------
// one warp per edge, each lane handles 4 cols
__global__ __launch_bounds__(256) void k_scatter(const int* __restrict__ src,
                                                 const int* __restrict__ dst,
                                                 int E) {
    int wid = (blockIdx.x * blockDim.x + threadIdx.x) >> 5;
    int lane = threadIdx.x & 31;
    if (wid >= E) return;
    int s = src[wid];
    int d = dst[wid];
    float w = g_dinv[s] * g_dinv[d];
    float4 v = reinterpret_cast<const float4*>(g_xw + (size_t)s * NF)[lane];
    float* od = g_h + (size_t)d * NF + lane * 4;
    atomicAdd(od + 0, w * v.x);
    atomicAdd(od + 1, w * v.y);
    atomicAdd(od + 2, w * v.z);
    atomicAdd(od + 3, w * v.w);
}

// ---------------- elementwise sigmoid on g_h ----------------
__global__ void k_sigmoid(int n) {
    int idx = blockIdx.x * blockDim.x + threadIdx.x;   // float4
    int total = n * (NF / 4);
    if (idx >= total) return;
    float4 v = reinterpret_cast<const float4*>(g_h)[idx];
    v.x = 1.f / (1.f + expf(-v.x));
    v.y = 1.f / (1.f + expf(-v.y));
    v.z = 1.f / (1.f + expf(-v.z));
    v.w = 1.f / (1.f + expf(-v.w));
    reinterpret_cast<float4*>(g_h)[idx] = v;
}

// ---------------- zero pooled accumulators ----------------
__global__ void k_zero_pool() {
    int i = blockIdx.x * blockDim.x + threadIdx.x;
    if (i < N_GRAPHS * NF) g_pooled[i] = 0.f;
    if (i < N_GRAPHS) g_cnt[i] = 0.f;
}

// ---------------- pooling (relu fused): segment-sum over sorted batch ----------------
#define POOL_NPB 256
__global__ __launch_bounds__(128) void k_pool(const int* __restrict__ batch, int n) {
    int col = threadIdx.x;   // 128 threads
    int start = blockIdx.x * POOL_NPB;
    if (start >= n) return;
    int end = min(start + POOL_NPB, n);
    int cur = batch[start];
    float acc = 0.f;
    int cnt = 0;
    for (int node = start; node < end; node++) {
        int g = batch[node];
        if (g != cur) {
            atomicAdd(&g_pooled[cur * NF + col], acc);
            if (col == 0) atomicAdd(&g_cnt[cur], (float)cnt);
            acc = 0.f; cnt = 0; cur = g;
        }
        float v = g_h[(size_t)node * NF + col];
        acc += fmaxf(v, 0.f);
        cnt++;
    }
    atomicAdd(&g_pooled[cur * NF + col], acc);
    if (col == 0) atomicAdd(&g_cnt[cur], (float)cnt);
}

// ---------------- final MLP: one block per graph ----------------
__global__ __launch_bounds__(64) void k_mlp(const float* __restrict__ ilW,
                                            const float* __restrict__ ilb,
                                            const float* __restrict__ h1W,
                                            const float* __restrict__ h1b,
                                            const float* __restrict__ olW,
                                            const float* __restrict__ olb,
                                            float* __restrict__ out) {
    int g = blockIdx.x;
    int t = threadIdx.x;   // 64
    __shared__ float p[NF], s1[64], s2[16];
    float cnt = fmaxf(g_cnt[g], 1.0f);
    p[t] = g_pooled[g * NF + t] / cnt;
    p[t + 64] = g_pooled[g * NF + 64 + t] / cnt;
    __syncthreads();
    float a = ilb[t];
#pragma unroll 8
    for (int k = 0; k < 128; k++) a = fmaf(p[k], ilW[k * 64 + t], a);
    s1[t] = 1.f / (1.f + expf(-a));
    __syncthreads();
    if (t < 16) {
        float b = h1b[t];
#pragma unroll
        for (int j = 0; j < 64; j++) b = fmaf(s1[j], h1W[j * 16 + t], b);
        s2[t] = fmaxf(b, 0.f);
    }
    __syncthreads();
    if (t == 0) {
        float o = olb[0];
#pragma unroll
        for (int i = 0; i < 16; i++) o = fmaf(s2[i], olW[i], o);
        out[g] = o;
    }
}

// ---------------- launch ----------------
extern "C" void kernel_launch(void* const* d_in, const int* in_sizes, int n_in,
                              void* d_out, int out_size) {
    const float* x    = (const float*)d_in[0];
    const float* W1   = (const float*)d_in[1];
    const float* b1   = (const float*)d_in[2];
    const float* W2   = (const float*)d_in[3];
    const float* b2   = (const float*)d_in[4];
    const float* ilW  = (const float*)d_in[5];
    const float* ilb  = (const float*)d_in[6];
    const float* h1W  = (const float*)d_in[7];
    const float* h1b  = (const float*)d_in[8];
    const float* olW  = (const float*)d_in[9];
    const float* olb  = (const float*)d_in[10];
    const int* ei     = (const int*)d_in[11];    // int32! (JAX x64 disabled)
    const int* batch  = (const int*)d_in[12];    // int32!
    float* out = (float*)d_out;

    const int n = in_sizes[0] / NF;
    const int E = in_sizes[11] / 2;
    const int* src = ei;
    const int* dst = ei + E;

    const int tpb = 256;
    const int nb_nodes  = (n + tpb - 1) / tpb;
    const int nb_edges  = (E + tpb - 1) / tpb;
    const int nb_gemm   = (n + 63) / 64;
    const int nb_elem4  = (n * (NF / 4) + tpb - 1) / tpb;
    const int nb_scat   = (int)(((long long)E * 32 + tpb - 1) / tpb);
    const int nb_pool   = (n + POOL_NPB - 1) / POOL_NPB;

    // degree + norm
    k_deg_init<<<nb_nodes, tpb>>>(n);
    k_deg_edges<<<nb_edges, tpb>>>(dst, E);
    k_dinv<<<nb_nodes, tpb>>>(n);

    // layer 1
    k_gemm<<<nb_gemm, 256>>>(x, W1, n, 0);
    k_selfinit<<<nb_elem4, tpb>>>(b1, n);
    k_scatter<<<nb_scat, 256>>>(src, dst, E);
    k_sigmoid<<<nb_elem4, tpb>>>(n);

    // layer 2
    k_gemm<<<nb_gemm, 256>>>(nullptr, W2, n, 1);
    k_selfinit<<<nb_elem4, tpb>>>(b2, n);
    k_scatter<<<nb_scat, 256>>>(src, dst, E);

    // pool (relu fused) + MLP
    k_zero_pool<<<(N_GRAPHS * NF + tpb - 1) / tpb, tpb>>>();
    k_pool<<<nb_pool, 128>>>(batch, n);
    k_mlp<<<N_GRAPHS, 64>>>(ilW, ilb, h1W, h1b, olW, olb, out);
}

// round 5
// speedup vs baseline: 1.7672x; 1.7672x over previous
#include <cuda_runtime.h>
#include <cuda_bf16.h>
#include <math.h>

#define MAX_NODES 50000
#define MAX_EDGES 800000
#define NF 128
#define N_GRAPHS 64
#define SCAN_T 1024

// ---------------- scratch (device-symbol globals; referenced ONLY in device code) ----------------
__device__ float g_dinv[MAX_NODES];
__device__ int   g_rowstart[MAX_NODES + 1];
__device__ int   g_fill[MAX_NODES];          // histogram, then fill cursor
__device__ int   g_csr_src[MAX_EDGES];
__device__ float g_xw[(size_t)MAX_NODES * NF];   // x@W result
__device__ float g_h[(size_t)MAX_NODES * NF];    // conv output
__device__ float g_pooled[N_GRAPHS * NF];
__device__ float g_cnt[N_GRAPHS];

// ---------------- CSR build ----------------
__global__ void k_zero_fill(int n) {
    int i = blockIdx.x * blockDim.x + threadIdx.x;
    if (i < n) g_fill[i] = 0;
}

__global__ void k_count(const int* __restrict__ dst, int E) {
    int i = blockIdx.x * blockDim.x + threadIdx.x;
    if (i < E) atomicAdd(&g_fill[dst[i]], 1);
}

// single-block exclusive scan over g_fill -> g_rowstart; also dinv = rsqrt(1+deg); reset fill
__global__ __launch_bounds__(SCAN_T) void k_scan(int n) {
    __shared__ int partial[SCAN_T];
    int t = threadIdx.x;
    int C = (n + SCAN_T - 1) / SCAN_T;
    int start = t * C;
    int end = min(start + C, n);
    int sum = 0;
    for (int i = start; i < end; i++) sum += g_fill[i];
    partial[t] = sum;
    __syncthreads();
    // Hillis-Steele inclusive scan on partials
    for (int off = 1; off < SCAN_T; off <<= 1) {
        int v = (t >= off) ? partial[t - off] : 0;
        __syncthreads();
        partial[t] += v;
        __syncthreads();
    }
    int offset = (t == 0) ? 0 : partial[t - 1];
    for (int i = start; i < end; i++) {
        int c = g_fill[i];
        g_rowstart[i] = offset;
        g_dinv[i] = rsqrtf(1.0f + (float)c);   // self-loop included
        g_fill[i] = 0;
        offset += c;
    }
    if (end == n && start < n) g_rowstart[n] = offset;
    if (n <= start && t == SCAN_T - 1) g_rowstart[n] = partial[SCAN_T - 1];
}

__global__ void k_bin(const int* __restrict__ src, const int* __restrict__ dst, int E) {
    int i = blockIdx.x * blockDim.x + threadIdx.x;
    if (i >= E) return;
    int d = dst[i];
    int p = g_rowstart[d] + atomicAdd(&g_fill[d], 1);
    g_csr_src[p] = src[i];
}

// ---------------- GEMM: g_xw[n,128] = A[n,128] @ W[128,128] ----------------
__global__ __launch_bounds__(256) void k_gemm(const float* __restrict__ A_ext,
                                              const float* __restrict__ W,
                                              int n, int fromH) {
    const float* A = fromH ? g_h : A_ext;
    __shared__ float As[64][NF];   // 32 KB
    __shared__ float Ws[32][NF];   // 16 KB
    const int tid = threadIdx.x;
    const int row0 = blockIdx.x * 64;
    const int tx = tid & 31;
    const int ty = tid >> 5;

    for (int i = tid; i < 64 * 32; i += 256) {
        int r = i >> 5, c4 = i & 31;
        float4 v = make_float4(0.f, 0.f, 0.f, 0.f);
        if (row0 + r < n)
            v = reinterpret_cast<const float4*>(A + (size_t)(row0 + r) * NF)[c4];
        *reinterpret_cast<float4*>(&As[r][c4 * 4]) = v;
    }

    float acc[8][4];
#pragma unroll
    for (int r = 0; r < 8; r++)
#pragma unroll
        for (int c = 0; c < 4; c++) acc[r][c] = 0.f;

    for (int kc = 0; kc < 4; kc++) {
        __syncthreads();
        for (int i = tid; i < 32 * 32; i += 256) {
            int r = i >> 5, c4 = i & 31;
            *reinterpret_cast<float4*>(&Ws[r][c4 * 4]) =
                reinterpret_cast<const float4*>(W + (size_t)(kc * 32 + r) * NF)[c4];
        }
        __syncthreads();
#pragma unroll
        for (int k = 0; k < 32; k++) {
            float4 w = *reinterpret_cast<const float4*>(&Ws[k][tx * 4]);
#pragma unroll
            for (int r = 0; r < 8; r++) {
                float a = As[ty * 8 + r][kc * 32 + k];
                acc[r][0] = fmaf(a, w.x, acc[r][0]);
                acc[r][1] = fmaf(a, w.y, acc[r][1]);
                acc[r][2] = fmaf(a, w.z, acc[r][2]);
                acc[r][3] = fmaf(a, w.w, acc[r][3]);
            }
        }
    }

#pragma unroll
    for (int r = 0; r < 8; r++) {
        int row = row0 + ty * 8 + r;
        if (row < n) {
            float4 v = make_float4(acc[r][0], acc[r][1], acc[r][2], acc[r][3]);
            reinterpret_cast<float4*>(g_xw + (size_t)row * NF)[tx] = v;
        }
    }
}

// ---------------- fused conv aggregation (gather, no atomics) ----------------
// one warp per node; act: 0=sigmoid, 1=relu
// out[d] = act( b + dinv[d] * ( dinv[d]*xw[d] + sum_{e: dst=d} dinv[src]*xw[src] ) )
__global__ __launch_bounds__(256) void k_gather(const float* __restrict__ b,
                                                int n, int act) {
    int node = (blockIdx.x * blockDim.x + threadIdx.x) >> 5;
    int lane = threadIdx.x & 31;
    if (node >= n) return;

    const int beg = g_rowstart[node];
    const int end = g_rowstart[node + 1];
    const float dd = g_dinv[node];

    // self-loop term
    float4 x0 = reinterpret_cast<const float4*>(g_xw + (size_t)node * NF)[lane];
    float4 acc = make_float4(dd * x0.x, dd * x0.y, dd * x0.z, dd * x0.w);

    // edges in chunks of 32: lane-parallel index+weight fetch, shfl broadcast
    for (int base = beg; base < end; base += 32) {
        int e = base + lane;
        int myidx = (e < end) ? g_csr_src[e] : -1;
        float myw = (myidx >= 0) ? g_dinv[myidx] : 0.f;
        int cnt = min(32, end - base);
#pragma unroll 4
        for (int j = 0; j < cnt; j++) {
            int s = __shfl_sync(0xFFFFFFFFu, myidx, j);
            float w = __shfl_sync(0xFFFFFFFFu, myw, j);
            float4 v = reinterpret_cast<const float4*>(g_xw + (size_t)s * NF)[lane];
            acc.x = fmaf(w, v.x, acc.x);
            acc.y = fmaf(w, v.y, acc.y);
            acc.z = fmaf(w, v.z, acc.z);
            acc.w = fmaf(w, v.w, acc.w);
        }
    }

    float4 bb = reinterpret_cast<const float4*>(b)[lane];
    float4 o;
    o.x = fmaf(dd, acc.x, bb.x);
    o.y = fmaf(dd, acc.y, bb.y);
    o.z = fmaf(dd, acc.z, bb.z);
    o.w = fmaf(dd, acc.w, bb.w);
    if (act == 0) {
        o.x = 1.f / (1.f + expf(-o.x));
        o.y = 1.f / (1.f + expf(-o.y));
        o.z = 1.f / (1.f + expf(-o.z));
        o.w = 1.f / (1.f + expf(-o.w));
    } else {
        o.x = fmaxf(o.x, 0.f);
        o.y = fmaxf(o.y, 0.f);
        o.z = fmaxf(o.z, 0.f);
        o.w = fmaxf(o.w, 0.f);
    }
    reinterpret_cast<float4*>(g_h + (size_t)node * NF)[lane] = o;
}

// ---------------- zero pooled accumulators ----------------
__global__ void k_zero_pool() {
    int i = blockIdx.x * blockDim.x + threadIdx.x;
    if (i < N_GRAPHS * NF) g_pooled[i] = 0.f;
    if (i < N_GRAPHS) g_cnt[i] = 0.f;
}

// ---------------- pooling: segment-sum over sorted batch (relu already applied) ----------------
#define POOL_NPB 256
__global__ __launch_bounds__(128) void k_pool(const int* __restrict__ batch, int n) {
    int col = threadIdx.x;
    int start = blockIdx.x * POOL_NPB;
    if (start >= n) return;
    int end = min(start + POOL_NPB, n);
    int cur = batch[start];
    float acc = 0.f;
    int cnt = 0;
    for (int node = start; node < end; node++) {
        int g = batch[node];
        if (g != cur) {
            atomicAdd(&g_pooled[cur * NF + col], acc);
            if (col == 0) atomicAdd(&g_cnt[cur], (float)cnt);
            acc = 0.f; cnt = 0; cur = g;
        }
        acc += g_h[(size_t)node * NF + col];
        cnt++;
    }
    atomicAdd(&g_pooled[cur * NF + col], acc);
    if (col == 0) atomicAdd(&g_cnt[cur], (float)cnt);
}

// ---------------- final MLP: one block per graph ----------------
__global__ __launch_bounds__(64) void k_mlp(const float* __restrict__ ilW,
                                            const float* __restrict__ ilb,
                                            const float* __restrict__ h1W,
                                            const float* __restrict__ h1b,
                                            const float* __restrict__ olW,
                                            const float* __restrict__ olb,
                                            float* __restrict__ out) {
    int g = blockIdx.x;
    int t = threadIdx.x;
    __shared__ float p[NF], s1[64], s2[16];
    float cnt = fmaxf(g_cnt[g], 1.0f);
    p[t] = g_pooled[g * NF + t] / cnt;
    p[t + 64] = g_pooled[g * NF + 64 + t] / cnt;
    __syncthreads();
    float a = ilb[t];
#pragma unroll 8
    for (int k = 0; k < 128; k++) a = fmaf(p[k], ilW[k * 64 + t], a);
    s1[t] = 1.f / (1.f + expf(-a));
    __syncthreads();
    if (t < 16) {
        float b = h1b[t];
#pragma unroll
        for (int j = 0; j < 64; j++) b = fmaf(s1[j], h1W[j * 16 + t], b);
        s2[t] = fmaxf(b, 0.f);
    }
    __syncthreads();
    if (t == 0) {
        float o = olb[0];
#pragma unroll
        for (int i = 0; i < 16; i++) o = fmaf(s2[i], olW[i], o);
        out[g] = o;
    }
}

// ---------------- launch ----------------
extern "C" void kernel_launch(void* const* d_in, const int* in_sizes, int n_in,
                              void* d_out, int out_size) {
    const float* x    = (const float*)d_in[0];
    const float* W1   = (const float*)d_in[1];
    const float* b1   = (const float*)d_in[2];
    const float* W2   = (const float*)d_in[3];
    const float* b2   = (const float*)d_in[4];
    const float* ilW  = (const float*)d_in[5];
    const float* ilb  = (const float*)d_in[6];
    const float* h1W  = (const float*)d_in[7];
    const float* h1b  = (const float*)d_in[8];
    const float* olW  = (const float*)d_in[9];
    const float* olb  = (const float*)d_in[10];
    const int* ei     = (const int*)d_in[11];    // int32 (JAX x64 disabled)
    const int* batch  = (const int*)d_in[12];
    float* out = (float*)d_out;

    const int n = in_sizes[0] / NF;
    const int E = in_sizes[11] / 2;
    const int* src = ei;
    const int* dst = ei + E;

    const int tpb = 256;
    const int nb_nodes = (n + tpb - 1) / tpb;
    const int nb_edges = (E + tpb - 1) / tpb;
    const int nb_gemm  = (n + 63) / 64;
    const int nb_warp  = (n * 32 + tpb - 1) / tpb;
    const int nb_pool  = (n + POOL_NPB - 1) / POOL_NPB;

    // CSR build (also computes dinv)
    k_zero_fill<<<nb_nodes, tpb>>>(n);
    k_count<<<nb_edges, tpb>>>(dst, E);
    k_scan<<<1, SCAN_T>>>(n);
    k_bin<<<nb_edges, tpb>>>(src, dst, E);

    // layer 1: gemm + fused gather/bias/sigmoid
    k_gemm<<<nb_gemm, 256>>>(x, W1, n, 0);
    k_gather<<<nb_warp, 256>>>(b1, n, 0);

    // layer 2: gemm + fused gather/bias/relu
    k_gemm<<<nb_gemm, 256>>>(nullptr, W2, n, 1);
    k_gather<<<nb_warp, 256>>>(b2, n, 1);

    // pool + MLP
    k_zero_pool<<<(N_GRAPHS * NF + tpb - 1) / tpb, tpb>>>();
    k_pool<<<nb_pool, 128>>>(batch, n);
    k_mlp<<<N_GRAPHS, 64>>>(ilW, ilb, h1W, h1b, olW, olb, out);
}